// round 16
// baseline (speedup 1.0000x reference)
#include <cuda_runtime.h>
#include <cuda_fp16.h>
#include <math.h>
#include <cstdint>

// Problem dims
constexpr int Bb = 4;
constexpr int Ss = 2048;
constexpr int Dd = 1024;
constexpr int Hh = 16;
constexpr int HD = 64;
constexpr int Mrows = Bb * Ss;          // 8192

// ---------------------------------------------------------------------------
// Device-global scratch (fp16 operands)
// ---------------------------------------------------------------------------
__device__ __half g_x16[(size_t)Mrows * Dd];
__device__ __half g_wa16[(size_t)3 * Dd * Dd];   // W_attn^T [3072,1024]
__device__ __half g_wp16[(size_t)Dd * Dd];       // W_proj^T [1024,1024]
__device__ __half g_q16[(size_t)Bb * Hh * Ss * HD];   // pre-scaled by 0.125*log2e
__device__ __half g_k16[(size_t)Bb * Hh * Ss * HD];
__device__ __half g_v16[(size_t)Bb * Hh * Ss * HD];
__device__ __half g_y16[(size_t)Mrows * Dd];

// ---------------------------------------------------------------------------
// Helpers
// ---------------------------------------------------------------------------
__device__ __forceinline__ uint32_t smem_u32(const void* p) {
    uint32_t a;
    asm("{ .reg .u64 t; cvta.to.shared.u64 t, %1; cvt.u32.u64 %0, t; }"
        : "=r"(a) : "l"(p));
    return a;
}

__device__ __forceinline__ void ldsm_x4(uint32_t (&r)[4], uint32_t addr) {
    asm volatile("ldmatrix.sync.aligned.m8n8.x4.shared.b16 {%0,%1,%2,%3}, [%4];"
        : "=r"(r[0]), "=r"(r[1]), "=r"(r[2]), "=r"(r[3]) : "r"(addr));
}
__device__ __forceinline__ void ldsm_x4t(uint32_t (&r)[4], uint32_t addr) {
    asm volatile("ldmatrix.sync.aligned.m8n8.x4.trans.shared.b16 {%0,%1,%2,%3}, [%4];"
        : "=r"(r[0]), "=r"(r[1]), "=r"(r[2]), "=r"(r[3]) : "r"(addr));
}
__device__ __forceinline__ void mma16816(float (&c)[4], const uint32_t (&a)[4],
                                         uint32_t b0, uint32_t b1) {
    asm volatile(
        "mma.sync.aligned.m16n8k16.row.col.f32.f16.f16.f32 "
        "{%0,%1,%2,%3}, {%4,%5,%6,%7}, {%8,%9}, {%0,%1,%2,%3};"
        : "+f"(c[0]), "+f"(c[1]), "+f"(c[2]), "+f"(c[3])
        : "r"(a[0]), "r"(a[1]), "r"(a[2]), "r"(a[3]), "r"(b0), "r"(b1));
}

#define CP16(dst, src) \
    asm volatile("cp.async.cg.shared.global [%0], [%1], 16;" :: "r"(dst), "l"(src))
#define CP_COMMIT() asm volatile("cp.async.commit_group;" ::: "memory")

__device__ __forceinline__ uint32_t pack2h(float v0, float v1) {
    __half2 h = __floats2half2_rn(v0, v1);
    return *(uint32_t*)&h;
}
// 2^x on packed half2
__device__ __forceinline__ uint32_t h2ex2(uint32_t x) {
    uint32_t r;
    asm volatile("ex2.approx.f16x2 %0, %1;" : "=r"(r) : "r"(x));
    return r;
}
constexpr uint32_t HONES = 0x3C003C00u;   // half2(1.0, 1.0)

// ---------------------------------------------------------------------------
// Fused prep: conv x -> fp16, transpose+conv W_attn and W_proj.
// ---------------------------------------------------------------------------
__global__ __launch_bounds__(256) void prep_kernel(
    const float* __restrict__ x,
    const float* __restrict__ Wa,
    const float* __restrict__ Wp)
{
    __shared__ float t[32][33];
    const int bid = blockIdx.x;
    const int tid = threadIdx.x;

    if (bid < 8192) {
        int i = bid * 256 + tid;
        float4 v = ((const float4*)x)[i];
        ((uint32_t*)g_x16)[i * 2 + 0] = pack2h(v.x, v.y);
        ((uint32_t*)g_x16)[i * 2 + 1] = pack2h(v.z, v.w);
        return;
    }
    const float* W;
    __half* Dst;
    int n0, k0, Ncols;
    if (bid < 8192 + 3072) {
        int tt = bid - 8192;
        W = Wa; Dst = g_wa16; Ncols = 3072;
        n0 = (tt % 96) * 32; k0 = (tt / 96) * 32;
    } else {
        int tt = bid - 11264;
        W = Wp; Dst = g_wp16; Ncols = 1024;
        n0 = (tt % 32) * 32; k0 = (tt / 32) * 32;
    }
    int tx = tid & 31, ty = tid >> 5;   // (32,8)
#pragma unroll
    for (int i = 0; i < 32; i += 8)
        t[ty + i][tx] = W[(size_t)(k0 + ty + i) * Ncols + n0 + tx];
    __syncthreads();
#pragma unroll
    for (int i = 0; i < 32; i += 8) {
        float v = t[tx][ty + i];
        Dst[(size_t)(n0 + ty + i) * 1024 + k0 + tx] = __float2half_rn(v);
    }
}

// ---------------------------------------------------------------------------
// QKV GEMM: block 128(M) x 384(N), 12 warps (2x6), warp tile 64x64.
// K-chunk 64, 3-stage cp.async pipeline, 1 barrier/kc, 1 CTA/SM.
// ---------------------------------------------------------------------------
constexpr int QSTRIDE = 144;
constexpr int QGA = 128 * QSTRIDE;            // 18432
constexpr int QGB = 384 * QSTRIDE;            // 55296
constexpr int QSTAGE = QGA + QGB;             // 73728
constexpr int QKV_SMEM = 3 * QSTAGE;          // 221184

__global__ __launch_bounds__(384) void qkv_kernel(const float* __restrict__ bias)
{
    extern __shared__ __align__(128) uint8_t smraw[];
    const uint32_t sb = smem_u32(smraw);
    const int tid = threadIdx.x;
    const int wid = tid >> 5, lane = tid & 31;
    const int wM = wid & 1, wN = wid >> 1;     // 2 (M) x 6 (N)
    const int lr = lane & 7, lm = lane >> 3;
    const int gq = lane >> 2, cq = lane & 3;
    const int bm = blockIdx.y * 128;
    const int bn = blockIdx.x * 384;

    float c[4][8][4];
#pragma unroll
    for (int a = 0; a < 4; a++)
#pragma unroll
        for (int b = 0; b < 8; b++)
#pragma unroll
            for (int d = 0; d < 4; d++) c[a][b][d] = 0.0f;

    auto fill = [&](int st, int kc) {
        uint32_t base = sb + st * QSTAGE;
        // A: rows [0,128) ; B: rows [128,512). 8 segs each. 4096 cp total.
        for (int i = tid; i < 4096; i += 384) {
            int row = i >> 3, seg = i & 7;
            if (row < 128) {
                CP16(base + row * QSTRIDE + seg * 16,
                     g_x16 + (size_t)(bm + row) * 1024 + kc * 64 + seg * 8);
            } else {
                int rb = row - 128;
                CP16(base + QGA + rb * QSTRIDE + seg * 16,
                     g_wa16 + (size_t)(bn + rb) * 1024 + kc * 64 + seg * 8);
            }
        }
        CP_COMMIT();
    };

    fill(0, 0);
    fill(1, 1);

    const uint32_t aOff = (uint32_t)((wM * 64 + (lm & 1) * 8 + lr) * QSTRIDE + (lm >> 1) * 16);
    const uint32_t bOff = (uint32_t)(QGA + (wN * 64 + (lm >> 1) * 8 + lr) * QSTRIDE + (lm & 1) * 16);

    int st = 0;
    for (int kc = 0; kc < 16; kc++) {
        if (kc == 15) asm volatile("cp.async.wait_group 0;" ::: "memory");
        else          asm volatile("cp.async.wait_group 1;" ::: "memory");
        __syncthreads();
        if (kc + 2 < 16) {
            int nst = st + 2; if (nst >= 3) nst -= 3;
            fill(nst, kc + 2);
        }

        const uint32_t base = sb + st * QSTAGE;
        const uint32_t aAd = base + aOff;
        const uint32_t bAd = base + bOff;

#pragma unroll
        for (int ks = 0; ks < 4; ks++) {
            uint32_t af[4][4];
#pragma unroll
            for (int mf = 0; mf < 4; mf++)
                ldsm_x4(af[mf], aAd + mf * 16 * QSTRIDE + ks * 32);
#pragma unroll
            for (int jjB = 0; jjB < 4; jjB++) {
                uint32_t bf[4];
                ldsm_x4(bf, bAd + jjB * 16 * QSTRIDE + ks * 32);
#pragma unroll
                for (int mf = 0; mf < 4; mf++)
#pragma unroll
                    for (int nn = 0; nn < 2; nn++)
                        mma16816(c[mf][jjB * 2 + nn], af[mf], bf[nn * 2], bf[nn * 2 + 1]);
            }
        }
        if (++st >= 3) st = 0;
    }

    // Epilogue: scatter q/k/v fp16 (Q pre-scaled for ex2 softmax)
#pragma unroll
    for (int mf = 0; mf < 4; mf++) {
        int row0 = bm + wM * 64 + mf * 16 + gq;
#pragma unroll
        for (int j = 0; j < 8; j++) {
            int n = bn + wN * 64 + j * 8 + 2 * cq;
            float b0 = bias[n], b1 = bias[n + 1];
            const int which = n >> 10;
            const int dd = n & 1023;
            const int h = dd >> 6, hd = dd & 63;
            __half* pq = (which == 0) ? g_q16 : (which == 1) ? g_k16 : g_v16;
            const float sc = (which == 0) ? 0.125f * 1.44269504f : 1.0f;
#pragma unroll
            for (int half_ = 0; half_ < 2; half_++) {
                int m = row0 + half_ * 8;
                int b_ = m >> 11, s_ = m & 2047;
                float v0 = (c[mf][j][half_ * 2 + 0] + b0) * sc;
                float v1 = (c[mf][j][half_ * 2 + 1] + b1) * sc;
                size_t idx = (((size_t)(b_ * Hh + h)) * Ss + s_) * HD + hd;
                *(uint32_t*)&pq[idx] = pack2h(v0, v1);
            }
        }
    }
}

// ---------------------------------------------------------------------------
// Proj GEMM (r13 config): block 128x128, 8 warps (32x64), K-chunk 64,
// 3-stage pipeline, 1 barrier/kc, 2 CTAs/SM.
// ---------------------------------------------------------------------------
constexpr int GSTRIDE = 144;
constexpr int GTILE = 128 * GSTRIDE;        // 18432
constexpr int GSTAGE = 2 * GTILE;           // 36864
constexpr int GEMM_SMEM = 3 * GSTAGE;       // 110592

__global__ __launch_bounds__(256, 2) void proj_kernel(const float* __restrict__ bias,
                                                      float* __restrict__ Out)
{
    extern __shared__ __align__(128) uint8_t smraw[];
    const uint32_t sb = smem_u32(smraw);
    const int tid = threadIdx.x;
    const int wid = tid >> 5, lane = tid & 31;
    const int wM = wid & 3, wN = wid >> 2;
    const int lr = lane & 7, lm = lane >> 3;
    const int gq = lane >> 2, cq = lane & 3;
    const int bm = blockIdx.y * 128;
    const int bn = blockIdx.x * 128;

    float c[2][8][4];
#pragma unroll
    for (int a = 0; a < 2; a++)
#pragma unroll
        for (int b = 0; b < 8; b++)
#pragma unroll
            for (int d = 0; d < 4; d++) c[a][b][d] = 0.0f;

    auto fill = [&](int st, int kc) {
        uint32_t base = sb + st * GSTAGE;
#pragma unroll
        for (int i = tid; i < 1024; i += 256) {
            int row = i >> 3, seg = i & 7;
            uint32_t off = (uint32_t)(row * GSTRIDE + seg * 16);
            CP16(base + off,         g_y16  + (size_t)(bm + row) * 1024 + kc * 64 + seg * 8);
            CP16(base + GTILE + off, g_wp16 + (size_t)(bn + row) * 1024 + kc * 64 + seg * 8);
        }
        CP_COMMIT();
    };

    fill(0, 0);
    fill(1, 1);

    int st = 0;
    for (int kc = 0; kc < 16; kc++) {
        if (kc == 15) asm volatile("cp.async.wait_group 0;" ::: "memory");
        else          asm volatile("cp.async.wait_group 1;" ::: "memory");
        __syncthreads();
        if (kc + 2 < 16) {
            int nst = st + 2; if (nst >= 3) nst -= 3;
            fill(nst, kc + 2);
        }

        const uint32_t base = sb + st * GSTAGE;
#pragma unroll
        for (int ks = 0; ks < 4; ks++) {
            uint32_t ah[2][4];
#pragma unroll
            for (int mf = 0; mf < 2; mf++) {
                int row = wM * 32 + mf * 16 + (lm & 1) * 8 + lr;
                int col = ks * 16 + (lm >> 1) * 8;
                ldsm_x4(ah[mf], base + row * GSTRIDE + col * 2);
            }
#pragma unroll
            for (int jj = 0; jj < 4; jj++) {
                int rowB = wN * 64 + jj * 16 + (lm >> 1) * 8 + lr;
                int colB = ks * 16 + (lm & 1) * 8;
                uint32_t bh_[4];
                ldsm_x4(bh_, base + GTILE + rowB * GSTRIDE + colB * 2);
#pragma unroll
                for (int mf = 0; mf < 2; mf++)
#pragma unroll
                    for (int nn = 0; nn < 2; nn++)
                        mma16816(c[mf][jj * 2 + nn], ah[mf], bh_[nn * 2], bh_[nn * 2 + 1]);
            }
        }
        if (++st >= 3) st = 0;
    }

#pragma unroll
    for (int mf = 0; mf < 2; mf++) {
        int row0 = bm + wM * 32 + mf * 16 + gq;
#pragma unroll
        for (int j = 0; j < 8; j++) {
            int n = bn + wN * 64 + j * 8 + 2 * cq;
            float b0 = bias[n], b1 = bias[n + 1];
#pragma unroll
            for (int half_ = 0; half_ < 2; half_++) {
                int m = row0 + half_ * 8;
                float2 o;
                o.x = c[mf][j][half_ * 2 + 0] + b0;
                o.y = c[mf][j][half_ * 2 + 1] + b1;
                *(float2*)&Out[(size_t)m * 1024 + n] = o;
            }
        }
    }
}

// ---------------------------------------------------------------------------
// Flash attention fp16 (r13): no-max ex2 softmax, ones-MMA rowsums.
// 256 thr = 8 warps, Q tile 128 rows, K/V tile 64, 3-stage pipeline.
// ---------------------------------------------------------------------------
constexpr int ATB = 64 * 144;                 // 9216 B per K/V array
constexpr int ATT_STAGE = 2 * ATB;            // 18432
constexpr int ATT_QOFF = 3 * ATT_STAGE;       // 55296
constexpr int ATT_QSZ = 128 * 144;            // 18432
constexpr int ATT_SMEM = ATT_QOFF + ATT_QSZ;  // 73728

__global__ __launch_bounds__(256, 2) void attn_kernel()
{
    extern __shared__ __align__(128) uint8_t smd[];
    const uint32_t sb = smem_u32(smd);
    const int qt = gridDim.x - 1 - blockIdx.x;   // heavy tiles first
    const int bh = blockIdx.y;
    const int tid = threadIdx.x;
    const int w = tid >> 5, lane = tid & 31;
    const int lr = lane & 7, lm = lane >> 3;
    const int gq = lane >> 2, cq = lane & 3;

    const size_t bhoff = (size_t)bh * Ss * HD;
    const uint32_t qb = sb + ATT_QOFF;

    {
        const uint4* q4 = (const uint4*)(g_q16 + bhoff + (size_t)qt * 128 * HD);
#pragma unroll
        for (int i = tid; i < 1024; i += 256) {
            int row = i >> 3, seg = i & 7;
            *(uint4*)(smd + ATT_QOFF + row * 144 + seg * 16) = q4[row * 8 + seg];
        }
    }

    const int NT = 2 * qt + 2;

    auto fill = [&](int st, int kt) {
        uint32_t base = sb + st * ATT_STAGE;
        const size_t ko = bhoff + (size_t)kt * 64 * HD;
#pragma unroll
        for (int t = 0; t < 2; t++) {
            int idx = tid + t * 256;
            int row = idx >> 3, seg = idx & 7;
            uint32_t o = (uint32_t)(row * 144 + seg * 16);
            size_t go = ko + (size_t)row * HD + seg * 8;
            CP16(base + o,       g_k16 + go);
            CP16(base + ATB + o, g_v16 + go);
        }
        CP_COMMIT();
    };

    fill(0, 0);
    if (NT > 1) fill(1, 1);

    float suml[4] = {0.0f, 0.0f, 0.0f, 0.0f};
    float acc[8][4];
#pragma unroll
    for (int j = 0; j < 8; j++)
#pragma unroll
        for (int d = 0; d < 4; d++) acc[j][d] = 0.0f;

    int st = 0;
    for (int kt = 0; kt < NT; kt++) {
        if (kt + 1 < NT) asm volatile("cp.async.wait_group 1;" ::: "memory");
        else             asm volatile("cp.async.wait_group 0;" ::: "memory");
        __syncthreads();
        if (kt + 2 < NT) {
            int nst = st + 2; if (nst >= 3) nst -= 3;
            fill(nst, kt + 2);
        }

        const uint32_t base = sb + st * ATT_STAGE;

        float s[8][4];
#pragma unroll
        for (int j = 0; j < 8; j++)
#pragma unroll
            for (int d = 0; d < 4; d++) s[j][d] = 0.0f;

#pragma unroll
        for (int ks = 0; ks < 4; ks++) {
            uint32_t qh_[4];
            {
                int rowQ = w * 16 + (lm & 1) * 8 + lr;
                int colQ = ks * 16 + (lm >> 1) * 8;
                ldsm_x4(qh_, qb + rowQ * 144 + colQ * 2);
            }
#pragma unroll
            for (int jj = 0; jj < 2; jj++) {
                uint32_t bh0[4], bh1[4];
                {
                    int rowB = jj * 32 + (lm >> 1) * 8 + lr;
                    int colB = ks * 16 + (lm & 1) * 8;
                    uint32_t adB = base + rowB * 144 + colB * 2;
                    ldsm_x4(bh0, adB);
                    ldsm_x4(bh1, adB + 16 * 144);
                }
                int j0 = jj * 4;
                mma16816(s[j0 + 0], qh_, bh0[0], bh0[1]);
                mma16816(s[j0 + 1], qh_, bh0[2], bh0[3]);
                mma16816(s[j0 + 2], qh_, bh1[0], bh1[1]);
                mma16816(s[j0 + 3], qh_, bh1[2], bh1[3]);
            }
        }

        if (kt * 64 + 63 > qt * 128 + w * 16) {
            int rg0 = qt * 128 + w * 16 + gq, rg1 = rg0 + 8;
#pragma unroll
            for (int j = 0; j < 8; j++) {
                int ck = kt * 64 + j * 8 + 2 * cq;
                if (ck > rg0)     s[j][0] = -1e30f;
                if (ck + 1 > rg0) s[j][1] = -1e30f;
                if (ck > rg1)     s[j][2] = -1e30f;
                if (ck + 1 > rg1) s[j][3] = -1e30f;
            }
        }

#pragma unroll
        for (int ks = 0; ks < 4; ks++) {
            uint32_t pa[4];
            pa[0] = h2ex2(pack2h(s[2 * ks][0],     s[2 * ks][1]));
            pa[1] = h2ex2(pack2h(s[2 * ks][2],     s[2 * ks][3]));
            pa[2] = h2ex2(pack2h(s[2 * ks + 1][0], s[2 * ks + 1][1]));
            pa[3] = h2ex2(pack2h(s[2 * ks + 1][2], s[2 * ks + 1][3]));

            mma16816(suml, pa, HONES, HONES);

#pragma unroll
            for (int jj = 0; jj < 2; jj++) {
                uint32_t vh0[4], vh1[4];
                {
                    int rowV = ks * 16 + (lm & 1) * 8 + lr;
                    int colV = jj * 32 + (lm >> 1) * 8;
                    uint32_t adV = base + ATB + rowV * 144 + colV * 2;
                    ldsm_x4t(vh0, adV);
                    ldsm_x4t(vh1, adV + 32);
                }
                int j0 = jj * 4;
                mma16816(acc[j0 + 0], pa, vh0[0], vh0[1]);
                mma16816(acc[j0 + 1], pa, vh0[2], vh0[3]);
                mma16816(acc[j0 + 2], pa, vh1[0], vh1[1]);
                mma16816(acc[j0 + 3], pa, vh1[2], vh1[3]);
            }
        }
        if (++st >= 3) st = 0;
    }

    float i0 = 1.0f / suml[0], i1 = 1.0f / suml[2];
    const int b_ = bh >> 4, h = bh & 15;
    const int sr0 = qt * 128 + w * 16 + gq, sr1 = sr0 + 8;
#pragma unroll
    for (int j = 0; j < 8; j++) {
        int hd = j * 8 + 2 * cq;
        size_t o0 = ((size_t)b_ * Ss + sr0) * Dd + h * HD + hd;
        *(uint32_t*)&g_y16[o0] = pack2h(acc[j][0] * i0, acc[j][1] * i0);
        size_t o1 = ((size_t)b_ * Ss + sr1) * Dd + h * HD + hd;
        *(uint32_t*)&g_y16[o1] = pack2h(acc[j][2] * i1, acc[j][3] * i1);
    }
}

// ---------------------------------------------------------------------------
extern "C" void kernel_launch(void* const* d_in, const int* in_sizes, int n_in,
                              void* d_out, int out_size)
{
    const float* x      = (const float*)d_in[0];
    const float* W_attn = (const float*)d_in[1];
    const float* b_attn = (const float*)d_in[2];
    const float* W_proj = (const float*)d_in[3];
    const float* b_proj = (const float*)d_in[4];
    float* out = (float*)d_out;

    cudaFuncSetAttribute(qkv_kernel,
                         cudaFuncAttributeMaxDynamicSharedMemorySize, QKV_SMEM);
    cudaFuncSetAttribute(proj_kernel,
                         cudaFuncAttributeMaxDynamicSharedMemorySize, GEMM_SMEM);
    cudaFuncSetAttribute(attn_kernel,
                         cudaFuncAttributeMaxDynamicSharedMemorySize, ATT_SMEM);

    // 0) fused prep
    prep_kernel<<<12288, 256>>>(x, W_attn, W_proj);

    // 1) QKV GEMM (128x384 blocks, 64x64 warp tiles) -> q/k/v fp16
    qkv_kernel<<<dim3(3072 / 384, Mrows / 128), 384, QKV_SMEM>>>(b_attn);

    // 2) causal flash attention -> y fp16
    attn_kernel<<<dim3(Ss / 128, Bb * Hh), 256, ATT_SMEM>>>();

    // 3) output projection -> out fp32
    proj_kernel<<<dim3(1024 / 128, Mrows / 128), 256, GEMM_SMEM>>>(b_proj, out);
}

// round 17
// speedup vs baseline: 1.0589x; 1.0589x over previous
#include <cuda_runtime.h>
#include <cuda_fp16.h>
#include <math.h>
#include <cstdint>

// Problem dims
constexpr int Bb = 4;
constexpr int Ss = 2048;
constexpr int Dd = 1024;
constexpr int Hh = 16;
constexpr int HD = 64;
constexpr int Mrows = Bb * Ss;          // 8192

// ---------------------------------------------------------------------------
// Device-global scratch (fp16 operands)
// ---------------------------------------------------------------------------
__device__ __half g_x16[(size_t)Mrows * Dd];
__device__ __half g_wa16[(size_t)3 * Dd * Dd];   // W_attn^T [3072,1024]
__device__ __half g_wp16[(size_t)Dd * Dd];       // W_proj^T [1024,1024]
__device__ __half g_q16[(size_t)Bb * Hh * Ss * HD];   // pre-scaled by 0.125*log2e
__device__ __half g_k16[(size_t)Bb * Hh * Ss * HD];
__device__ __half g_v16[(size_t)Bb * Hh * Ss * HD];
__device__ __half g_y16[(size_t)Mrows * Dd];

// ---------------------------------------------------------------------------
// Helpers
// ---------------------------------------------------------------------------
__device__ __forceinline__ uint32_t smem_u32(const void* p) {
    uint32_t a;
    asm("{ .reg .u64 t; cvta.to.shared.u64 t, %1; cvt.u32.u64 %0, t; }"
        : "=r"(a) : "l"(p));
    return a;
}

__device__ __forceinline__ void ldsm_x4(uint32_t (&r)[4], uint32_t addr) {
    asm volatile("ldmatrix.sync.aligned.m8n8.x4.shared.b16 {%0,%1,%2,%3}, [%4];"
        : "=r"(r[0]), "=r"(r[1]), "=r"(r[2]), "=r"(r[3]) : "r"(addr));
}
__device__ __forceinline__ void ldsm_x4t(uint32_t (&r)[4], uint32_t addr) {
    asm volatile("ldmatrix.sync.aligned.m8n8.x4.trans.shared.b16 {%0,%1,%2,%3}, [%4];"
        : "=r"(r[0]), "=r"(r[1]), "=r"(r[2]), "=r"(r[3]) : "r"(addr));
}
__device__ __forceinline__ void mma16816(float (&c)[4], const uint32_t (&a)[4],
                                         uint32_t b0, uint32_t b1) {
    asm volatile(
        "mma.sync.aligned.m16n8k16.row.col.f32.f16.f16.f32 "
        "{%0,%1,%2,%3}, {%4,%5,%6,%7}, {%8,%9}, {%0,%1,%2,%3};"
        : "+f"(c[0]), "+f"(c[1]), "+f"(c[2]), "+f"(c[3])
        : "r"(a[0]), "r"(a[1]), "r"(a[2]), "r"(a[3]), "r"(b0), "r"(b1));
}

#define CP16(dst, src) \
    asm volatile("cp.async.cg.shared.global [%0], [%1], 16;" :: "r"(dst), "l"(src))
#define CP_COMMIT() asm volatile("cp.async.commit_group;" ::: "memory")

__device__ __forceinline__ uint32_t pack2h(float v0, float v1) {
    __half2 h = __floats2half2_rn(v0, v1);
    return *(uint32_t*)&h;
}
// 2^x on packed half2
__device__ __forceinline__ uint32_t h2ex2(uint32_t x) {
    uint32_t r;
    asm volatile("ex2.approx.f16x2 %0, %1;" : "=r"(r) : "r"(x));
    return r;
}
constexpr uint32_t HONES = 0x3C003C00u;   // half2(1.0, 1.0)

// ---------------------------------------------------------------------------
// Fused prep: conv x -> fp16, transpose+conv W_attn and W_proj.
// ---------------------------------------------------------------------------
__global__ __launch_bounds__(256) void prep_kernel(
    const float* __restrict__ x,
    const float* __restrict__ Wa,
    const float* __restrict__ Wp)
{
    __shared__ float t[32][33];
    const int bid = blockIdx.x;
    const int tid = threadIdx.x;

    if (bid < 8192) {
        int i = bid * 256 + tid;
        float4 v = ((const float4*)x)[i];
        ((uint32_t*)g_x16)[i * 2 + 0] = pack2h(v.x, v.y);
        ((uint32_t*)g_x16)[i * 2 + 1] = pack2h(v.z, v.w);
        return;
    }
    const float* W;
    __half* Dst;
    int n0, k0, Ncols;
    if (bid < 8192 + 3072) {
        int tt = bid - 8192;
        W = Wa; Dst = g_wa16; Ncols = 3072;
        n0 = (tt % 96) * 32; k0 = (tt / 96) * 32;
    } else {
        int tt = bid - 11264;
        W = Wp; Dst = g_wp16; Ncols = 1024;
        n0 = (tt % 32) * 32; k0 = (tt / 32) * 32;
    }
    int tx = tid & 31, ty = tid >> 5;   // (32,8)
#pragma unroll
    for (int i = 0; i < 32; i += 8)
        t[ty + i][tx] = W[(size_t)(k0 + ty + i) * Ncols + n0 + tx];
    __syncthreads();
#pragma unroll
    for (int i = 0; i < 32; i += 8) {
        float v = t[tx][ty + i];
        Dst[(size_t)(n0 + ty + i) * 1024 + k0 + tx] = __float2half_rn(v);
    }
}

// ---------------------------------------------------------------------------
// mma.sync fp16 GEMM (r13 config): block 128x128, 8 warps (32x64 warp tile),
// K-chunk 64, 3-stage cp.async pipeline, 1 barrier/kc, 2 CTAs/SM.
// MODE 0: scatter q/k/v fp16. MODE 1: fp32 out.
// ---------------------------------------------------------------------------
constexpr int GSTRIDE = 144;
constexpr int GTILE = 128 * GSTRIDE;        // 18432
constexpr int GSTAGE = 2 * GTILE;           // 36864
constexpr int GEMM_SMEM = 3 * GSTAGE;       // 110592 (3 stages)

template <int NTOT, int MODE>
__global__ __launch_bounds__(256, 2) void mgemm_kernel(const float* __restrict__ bias,
                                                       float* __restrict__ Out)
{
    extern __shared__ __align__(128) uint8_t smraw[];
    const uint32_t sb = smem_u32(smraw);
    const int tid = threadIdx.x;
    const int wid = tid >> 5, lane = tid & 31;
    const int wM = wid & 3, wN = wid >> 2;
    const int lr = lane & 7, lm = lane >> 3;
    const int gq = lane >> 2, cq = lane & 3;
    const int bm = blockIdx.y * 128;
    const int bn = blockIdx.x * 128;

    const __half* __restrict__ A = (MODE == 0) ? g_x16 : g_y16;
    const __half* __restrict__ B = (MODE == 0) ? g_wa16 : g_wp16;

    float c[2][8][4];
#pragma unroll
    for (int a = 0; a < 2; a++)
#pragma unroll
        for (int b = 0; b < 8; b++)
#pragma unroll
            for (int d = 0; d < 4; d++) c[a][b][d] = 0.0f;

    auto fill = [&](int st, int kc) {
        uint32_t base = sb + st * GSTAGE;
#pragma unroll
        for (int i = tid; i < 1024; i += 256) {
            int row = i >> 3, seg = i & 7;
            uint32_t off = (uint32_t)(row * GSTRIDE + seg * 16);
            size_t ga = (size_t)(bm + row) * 1024 + kc * 64 + seg * 8;
            size_t gb = (size_t)(bn + row) * 1024 + kc * 64 + seg * 8;
            CP16(base + off,         A + ga);
            CP16(base + GTILE + off, B + gb);
        }
        CP_COMMIT();
    };

    fill(0, 0);
    fill(1, 1);

    int st = 0;
    for (int kc = 0; kc < 16; kc++) {
        if (kc == 15) asm volatile("cp.async.wait_group 0;" ::: "memory");
        else          asm volatile("cp.async.wait_group 1;" ::: "memory");
        __syncthreads();
        if (kc + 2 < 16) {
            int nst = st + 2; if (nst >= 3) nst -= 3;
            fill(nst, kc + 2);
        }

        const uint32_t base = sb + st * GSTAGE;
#pragma unroll
        for (int ks = 0; ks < 4; ks++) {
            uint32_t ah[2][4];
#pragma unroll
            for (int mf = 0; mf < 2; mf++) {
                int row = wM * 32 + mf * 16 + (lm & 1) * 8 + lr;
                int col = ks * 16 + (lm >> 1) * 8;
                ldsm_x4(ah[mf], base + row * GSTRIDE + col * 2);
            }
#pragma unroll
            for (int jj = 0; jj < 4; jj++) {
                int rowB = wN * 64 + jj * 16 + (lm >> 1) * 8 + lr;
                int colB = ks * 16 + (lm & 1) * 8;
                uint32_t bh_[4];
                ldsm_x4(bh_, base + GTILE + rowB * GSTRIDE + colB * 2);
#pragma unroll
                for (int mf = 0; mf < 2; mf++)
#pragma unroll
                    for (int nn = 0; nn < 2; nn++)
                        mma16816(c[mf][jj * 2 + nn], ah[mf], bh_[nn * 2], bh_[nn * 2 + 1]);
            }
        }
        if (++st >= 3) st = 0;
    }

    // Epilogue
#pragma unroll
    for (int mf = 0; mf < 2; mf++) {
        int row0 = bm + wM * 32 + mf * 16 + gq;
#pragma unroll
        for (int j = 0; j < 8; j++) {
            int n = bn + wN * 64 + j * 8 + 2 * cq;
            if (MODE == 0) {
                float b0 = bias[n], b1 = bias[n + 1];
                const int which = n >> 10;
                const int dd = n & 1023;
                const int h = dd >> 6, hd = dd & 63;
                __half* pq = (which == 0) ? g_q16 : (which == 1) ? g_k16 : g_v16;
                // Q scale folds softmax 1/8 AND log2e (for ex2-based softmax)
                const float sc = (which == 0) ? 0.125f * 1.44269504f : 1.0f;
#pragma unroll
                for (int half_ = 0; half_ < 2; half_++) {
                    int m = row0 + half_ * 8;
                    int b_ = m >> 11, s_ = m & 2047;
                    float v0 = (c[mf][j][half_ * 2 + 0] + b0) * sc;
                    float v1 = (c[mf][j][half_ * 2 + 1] + b1) * sc;
                    size_t idx = (((size_t)(b_ * Hh + h)) * Ss + s_) * HD + hd;
                    *(uint32_t*)&pq[idx] = pack2h(v0, v1);
                }
            } else {
                float b0 = bias[n], b1 = bias[n + 1];
#pragma unroll
                for (int half_ = 0; half_ < 2; half_++) {
                    int m = row0 + half_ * 8;
                    float2 o;
                    o.x = c[mf][j][half_ * 2 + 0] + b0;
                    o.y = c[mf][j][half_ * 2 + 1] + b1;
                    *(float2*)&Out[(size_t)m * NTOT + n] = o;
                }
            }
        }
    }
}

// ---------------------------------------------------------------------------
// Flash attention fp16, no-max ex2 softmax, ones-MMA rowsums.
// 256 thr = 8 warps, Q tile 128 rows, K/V tile 64, 3-stage pipeline.
// NEW: Q fragments cached in registers for the whole kt-loop (no per-kt ldsm).
// ---------------------------------------------------------------------------
constexpr int ATB = 64 * 144;                 // 9216 B per K/V array
constexpr int ATT_STAGE = 2 * ATB;            // 18432
constexpr int ATT_QOFF = 3 * ATT_STAGE;       // 55296
constexpr int ATT_QSZ = 128 * 144;            // 18432
constexpr int ATT_SMEM = ATT_QOFF + ATT_QSZ;  // 73728

__global__ __launch_bounds__(256, 2) void attn_kernel()
{
    extern __shared__ __align__(128) uint8_t smd[];
    const uint32_t sb = smem_u32(smd);
    const int qt = gridDim.x - 1 - blockIdx.x;   // heavy tiles first
    const int bh = blockIdx.y;
    const int tid = threadIdx.x;
    const int w = tid >> 5, lane = tid & 31;
    const int lr = lane & 7, lm = lane >> 3;
    const int gq = lane >> 2, cq = lane & 3;

    const size_t bhoff = (size_t)bh * Ss * HD;
    const uint32_t qb = sb + ATT_QOFF;

    // stage Q tile (128 rows x 64 halves)
    {
        const uint4* q4 = (const uint4*)(g_q16 + bhoff + (size_t)qt * 128 * HD);
#pragma unroll
        for (int i = tid; i < 1024; i += 256) {
            int row = i >> 3, seg = i & 7;
            *(uint4*)(smd + ATT_QOFF + row * 144 + seg * 16) = q4[row * 8 + seg];
        }
    }

    const int NT = 2 * qt + 2;

    auto fill = [&](int st, int kt) {
        uint32_t base = sb + st * ATT_STAGE;
        const size_t ko = bhoff + (size_t)kt * 64 * HD;
#pragma unroll
        for (int t = 0; t < 2; t++) {
            int idx = tid + t * 256;
            int row = idx >> 3, seg = idx & 7;
            uint32_t o = (uint32_t)(row * 144 + seg * 16);
            size_t go = ko + (size_t)row * HD + seg * 8;
            CP16(base + o,       g_k16 + go);
            CP16(base + ATB + o, g_v16 + go);
        }
        CP_COMMIT();
    };

    fill(0, 0);
    if (NT > 1) fill(1, 1);

    // Q fragments: load ONCE into registers (16 regs), reuse for all kt.
    __syncthreads();   // Q staging visible to all warps
    uint32_t qf[4][4];
#pragma unroll
    for (int ks = 0; ks < 4; ks++) {
        int rowQ = w * 16 + (lm & 1) * 8 + lr;
        int colQ = ks * 16 + (lm >> 1) * 8;
        ldsm_x4(qf[ks], qb + rowQ * 144 + colQ * 2);
    }

    float suml[4] = {0.0f, 0.0f, 0.0f, 0.0f};
    float acc[8][4];
#pragma unroll
    for (int j = 0; j < 8; j++)
#pragma unroll
        for (int d = 0; d < 4; d++) acc[j][d] = 0.0f;

    int st = 0;
    for (int kt = 0; kt < NT; kt++) {
        if (kt + 1 < NT) asm volatile("cp.async.wait_group 1;" ::: "memory");
        else             asm volatile("cp.async.wait_group 0;" ::: "memory");
        __syncthreads();
        if (kt + 2 < NT) {
            int nst = st + 2; if (nst >= 3) nst -= 3;
            fill(nst, kt + 2);
        }

        const uint32_t base = sb + st * ATT_STAGE;

        // S' = Qs @ K^T (log2-domain logits)
        float s[8][4];
#pragma unroll
        for (int j = 0; j < 8; j++)
#pragma unroll
            for (int d = 0; d < 4; d++) s[j][d] = 0.0f;

#pragma unroll
        for (int ks = 0; ks < 4; ks++) {
#pragma unroll
            for (int jj = 0; jj < 2; jj++) {
                uint32_t bh0[4], bh1[4];
                {
                    int rowB = jj * 32 + (lm >> 1) * 8 + lr;
                    int colB = ks * 16 + (lm & 1) * 8;
                    uint32_t adB = base + rowB * 144 + colB * 2;
                    ldsm_x4(bh0, adB);
                    ldsm_x4(bh1, adB + 16 * 144);
                }
                int j0 = jj * 4;
                mma16816(s[j0 + 0], qf[ks], bh0[0], bh0[1]);
                mma16816(s[j0 + 1], qf[ks], bh0[2], bh0[3]);
                mma16816(s[j0 + 2], qf[ks], bh1[0], bh1[1]);
                mma16816(s[j0 + 3], qf[ks], bh1[2], bh1[3]);
            }
        }

        // causal mask (masked -> -1e30 -> -inf fp16 -> 2^-inf = 0)
        if (kt * 64 + 63 > qt * 128 + w * 16) {
            int rg0 = qt * 128 + w * 16 + gq, rg1 = rg0 + 8;
#pragma unroll
            for (int j = 0; j < 8; j++) {
                int ck = kt * 64 + j * 8 + 2 * cq;
                if (ck > rg0)     s[j][0] = -1e30f;
                if (ck + 1 > rg0) s[j][1] = -1e30f;
                if (ck > rg1)     s[j][2] = -1e30f;
                if (ck + 1 > rg1) s[j][3] = -1e30f;
            }
        }

        // P = 2^(S') in half2; rowsums via ones-mma; O += P @ V
#pragma unroll
        for (int ks = 0; ks < 4; ks++) {
            uint32_t pa[4];
            pa[0] = h2ex2(pack2h(s[2 * ks][0],     s[2 * ks][1]));
            pa[1] = h2ex2(pack2h(s[2 * ks][2],     s[2 * ks][3]));
            pa[2] = h2ex2(pack2h(s[2 * ks + 1][0], s[2 * ks + 1][1]));
            pa[3] = h2ex2(pack2h(s[2 * ks + 1][2], s[2 * ks + 1][3]));

            mma16816(suml, pa, HONES, HONES);

#pragma unroll
            for (int jj = 0; jj < 2; jj++) {
                uint32_t vh0[4], vh1[4];
                {
                    int rowV = ks * 16 + (lm & 1) * 8 + lr;
                    int colV = jj * 32 + (lm >> 1) * 8;
                    uint32_t adV = base + ATB + rowV * 144 + colV * 2;
                    ldsm_x4t(vh0, adV);
                    ldsm_x4t(vh1, adV + 32);
                }
                int j0 = jj * 4;
                mma16816(acc[j0 + 0], pa, vh0[0], vh0[1]);
                mma16816(acc[j0 + 1], pa, vh0[2], vh0[3]);
                mma16816(acc[j0 + 2], pa, vh1[0], vh1[1]);
                mma16816(acc[j0 + 3], pa, vh1[2], vh1[3]);
            }
        }
        if (++st >= 3) st = 0;
    }

    // epilogue: normalize by rowsums, convert, store y fp16
    float i0 = 1.0f / suml[0], i1 = 1.0f / suml[2];
    const int b_ = bh >> 4, h = bh & 15;
    const int sr0 = qt * 128 + w * 16 + gq, sr1 = sr0 + 8;
#pragma unroll
    for (int j = 0; j < 8; j++) {
        int hd = j * 8 + 2 * cq;
        size_t o0 = ((size_t)b_ * Ss + sr0) * Dd + h * HD + hd;
        *(uint32_t*)&g_y16[o0] = pack2h(acc[j][0] * i0, acc[j][1] * i0);
        size_t o1 = ((size_t)b_ * Ss + sr1) * Dd + h * HD + hd;
        *(uint32_t*)&g_y16[o1] = pack2h(acc[j][2] * i1, acc[j][3] * i1);
    }
}

// ---------------------------------------------------------------------------
extern "C" void kernel_launch(void* const* d_in, const int* in_sizes, int n_in,
                              void* d_out, int out_size)
{
    const float* x      = (const float*)d_in[0];
    const float* W_attn = (const float*)d_in[1];
    const float* b_attn = (const float*)d_in[2];
    const float* W_proj = (const float*)d_in[3];
    const float* b_proj = (const float*)d_in[4];
    float* out = (float*)d_out;

    cudaFuncSetAttribute(mgemm_kernel<3072, 0>,
                         cudaFuncAttributeMaxDynamicSharedMemorySize, GEMM_SMEM);
    cudaFuncSetAttribute(mgemm_kernel<1024, 1>,
                         cudaFuncAttributeMaxDynamicSharedMemorySize, GEMM_SMEM);
    cudaFuncSetAttribute(attn_kernel,
                         cudaFuncAttributeMaxDynamicSharedMemorySize, ATT_SMEM);

    // 0) fused prep
    prep_kernel<<<12288, 256>>>(x, W_attn, W_proj);

    // 1) QKV GEMM -> q/k/v fp16 (Q pre-scaled for ex2 softmax)
    mgemm_kernel<3072, 0><<<dim3(3072 / 128, Mrows / 128), 256, GEMM_SMEM>>>(
        b_attn, nullptr);

    // 2) causal flash attention -> y fp16
    attn_kernel<<<dim3(Ss / 128, Bb * Hh), 256, ATT_SMEM>>>();

    // 3) output projection -> out fp32
    mgemm_kernel<1024, 1><<<dim3(1024 / 128, Mrows / 128), 256, GEMM_SMEM>>>(
        b_proj, out);
}